// round 5
// baseline (speedup 1.0000x reference)
#include <cuda_runtime.h>
#include <cuda_bf16.h>
#include <mma.h>
#include <cstdint>

using namespace nvcuda;

// Problem constants
constexpr int B = 2, S = 2048, D = 1024, H = 16, HD = 64;
constexpr size_t NEL = (size_t)B * S * D;   // 4194304
constexpr size_t WEL = (size_t)D * D;       // 1048576

// ---------------- scratch arena ----------------
constexpr size_t OFF_IN_HI  = 0;
constexpr size_t OFF_IN_LO  = OFF_IN_HI  + 3 * NEL * 2;
constexpr size_t OFF_W_HI   = OFF_IN_LO  + 3 * NEL * 2;
constexpr size_t OFF_W_LO   = OFF_W_HI   + 4 * WEL * 2;
constexpr size_t OFF_QKV_HI = OFF_W_LO   + 4 * WEL * 2;
constexpr size_t OFF_QKV_LO = OFF_QKV_HI + 3 * NEL * 2;
constexpr size_t OFF_XH_HI  = OFF_QKV_LO + 3 * NEL * 2;
constexpr size_t OFF_XH_LO  = OFF_XH_HI  + NEL * 2;
constexpr size_t OFF_LINV   = OFF_XH_LO  + NEL * 2;   // f32 [B*H*S]
constexpr size_t ARENA_BYTES = OFF_LINV + (size_t)B * H * S * 4;

__device__ __align__(256) unsigned char g_arena[ARENA_BYTES];

#define CP_ASYNC16(dst, src) asm volatile("cp.async.cg.shared.global [%0], [%1], 16;\n" :: "r"(dst), "l"(src))
#define CP_COMMIT()  asm volatile("cp.async.commit_group;\n" ::: "memory")
#define CP_WAIT1()   asm volatile("cp.async.wait_group 1;\n" ::: "memory")
#define CP_WAIT2()   asm volatile("cp.async.wait_group 2;\n" ::: "memory")

// ---------------- split fp32 -> bf16 hi/lo ----------------
__global__ void split_kernel(const float* __restrict__ src,
                             size_t hi_off, size_t lo_off, int n)
{
    int i = blockIdx.x * blockDim.x + threadIdx.x;
    if (i >= n) return;
    __nv_bfloat16* hi = (__nv_bfloat16*)(g_arena + hi_off);
    __nv_bfloat16* lo = (__nv_bfloat16*)(g_arena + lo_off);
    float x = src[i];
    __nv_bfloat16 h = __float2bfloat16(x);
    hi[i] = h;
    lo[i] = __float2bfloat16(x - __bfloat162float(h));
}

// ---------------- GEMM (unchanged from R4): 128x64 tile, 3-stage ----------
constexpr int G_SA  = 128 * 40 * 2;
constexpr int G_SB  = 64 * 40 * 2;
constexpr int G_STG = 2 * G_SA + 2 * G_SB;
constexpr int GEMM_SMEM = 3 * G_STG;

__global__ __launch_bounds__(256) void gemm_kernel(
    size_t ahi_off, size_t alo_off, size_t whi_off, size_t wlo_off,
    const float* __restrict__ bias,
    float* __restrict__ cext, size_t hi_off, size_t lo_off)
{
    const __nv_bfloat16* Ahi = (const __nv_bfloat16*)(g_arena + ahi_off);
    const __nv_bfloat16* Alo = (const __nv_bfloat16*)(g_arena + alo_off);
    const __nv_bfloat16* Whi = (const __nv_bfloat16*)(g_arena + whi_off);
    const __nv_bfloat16* Wlo = (const __nv_bfloat16*)(g_arena + wlo_off);

    extern __shared__ unsigned char smraw[];

    int m0 = blockIdx.y * 128, n0 = blockIdx.x * 64;
    int tid = threadIdx.x, wid = tid >> 5;
    int wm = wid & 3, wn = wid >> 2;

    auto fill = [&](int st, int kt) {
        int k0 = kt * 32;
        __nv_bfloat16* Ah = (__nv_bfloat16*)(smraw + st * G_STG);
        __nv_bfloat16* Al = (__nv_bfloat16*)(smraw + st * G_STG + G_SA);
        __nv_bfloat16* Bh = (__nv_bfloat16*)(smraw + st * G_STG + 2 * G_SA);
        __nv_bfloat16* Bl = (__nv_bfloat16*)(smraw + st * G_STG + 2 * G_SA + G_SB);
#pragma unroll
        for (int i = 0; i < 2; i++) {
            int v = tid + 256 * i;
            int r = v >> 2, c = (v & 3) * 8;
            size_t g = (size_t)(m0 + r) * D + k0 + c;
            CP_ASYNC16((unsigned)__cvta_generic_to_shared(Ah + r * 40 + c), Ahi + g);
            CP_ASYNC16((unsigned)__cvta_generic_to_shared(Al + r * 40 + c), Alo + g);
        }
        {
            int r = tid >> 2, c = (tid & 3) * 8;
            size_t g = (size_t)(n0 + r) * D + k0 + c;
            CP_ASYNC16((unsigned)__cvta_generic_to_shared(Bh + r * 40 + c), Whi + g);
            CP_ASYNC16((unsigned)__cvta_generic_to_shared(Bl + r * 40 + c), Wlo + g);
        }
    };

    wmma::fragment<wmma::accumulator, 16, 16, 16, float> acc[2][2];
#pragma unroll
    for (int i = 0; i < 2; i++)
#pragma unroll
        for (int j = 0; j < 2; j++) wmma::fill_fragment(acc[i][j], 0.0f);

    fill(0, 0); CP_COMMIT();
    fill(1, 1); CP_COMMIT();
    for (int kt = 0; kt < 32; kt++) {
        if (kt + 2 < 32) fill((kt + 2) % 3, kt + 2);
        CP_COMMIT();
        CP_WAIT2();
        __syncthreads();
        int st = kt % 3;
        const __nv_bfloat16* Ah = (const __nv_bfloat16*)(smraw + st * G_STG);
        const __nv_bfloat16* Al = (const __nv_bfloat16*)(smraw + st * G_STG + G_SA);
        const __nv_bfloat16* Bh = (const __nv_bfloat16*)(smraw + st * G_STG + 2 * G_SA);
        const __nv_bfloat16* Bl = (const __nv_bfloat16*)(smraw + st * G_STG + 2 * G_SA + G_SB);
#pragma unroll
        for (int kk = 0; kk < 32; kk += 16) {
            wmma::fragment<wmma::matrix_a, 16, 16, 16, __nv_bfloat16, wmma::row_major> ah[2], al[2];
            wmma::fragment<wmma::matrix_b, 16, 16, 16, __nv_bfloat16, wmma::col_major> bh[2], bl[2];
#pragma unroll
            for (int i = 0; i < 2; i++) {
                wmma::load_matrix_sync(ah[i], Ah + (wm * 32 + i * 16) * 40 + kk, 40);
                wmma::load_matrix_sync(al[i], Al + (wm * 32 + i * 16) * 40 + kk, 40);
            }
#pragma unroll
            for (int j = 0; j < 2; j++) {
                wmma::load_matrix_sync(bh[j], Bh + (wn * 32 + j * 16) * 40 + kk, 40);
                wmma::load_matrix_sync(bl[j], Bl + (wn * 32 + j * 16) * 40 + kk, 40);
            }
#pragma unroll
            for (int i = 0; i < 2; i++)
#pragma unroll
                for (int j = 0; j < 2; j++) {
                    wmma::mma_sync(acc[i][j], ah[i], bh[j], acc[i][j]);
                    wmma::mma_sync(acc[i][j], ah[i], bl[j], acc[i][j]);
                    wmma::mma_sync(acc[i][j], al[i], bh[j], acc[i][j]);
                }
        }
        __syncthreads();
    }

    float* Cs = (float*)smraw;
    __syncthreads();
#pragma unroll
    for (int i = 0; i < 2; i++)
#pragma unroll
        for (int j = 0; j < 2; j++)
            wmma::store_matrix_sync(Cs + (wm * 32 + i * 16) * 68 + wn * 32 + j * 16,
                                    acc[i][j], 68, wmma::mem_row_major);
    __syncthreads();

    __nv_bfloat16* hi = (__nv_bfloat16*)(g_arena + hi_off);
    __nv_bfloat16* lo = (__nv_bfloat16*)(g_arena + lo_off);
#pragma unroll
    for (int i = 0; i < 32; i++) {
        int v = tid + 256 * i;
        int r = v >> 6, c = v & 63;
        float x = Cs[r * 68 + c] + bias[n0 + c];
        size_t g = (size_t)(m0 + r) * D + n0 + c;
        if (cext) {
            cext[g] = x;
        } else {
            __nv_bfloat16 h = __float2bfloat16(x);
            hi[g] = h;
            lo[g] = __float2bfloat16(x - __bfloat162float(h));
        }
    }
}

// ---------------- single-pass attention (max-free softmax) ----------------
// CTA = 128 q-rows of one (b,h), 8 warps. Per 64-col K/V tile:
//   S = QK^T/8 (3-product), p' = exp(S) (masked), write p' raw to attn gmem,
//   accumulate row sums, P' hi/lo -> O += P'V (3-product).
// End: l-merge, O *= 1/l -> XH hi/lo, store 1/l for the normalize kernel.
constexpr int A_Q    = 0;                          // Qh[128][72], Ql
constexpr int A_QL   = A_Q   + 128 * 72 * 2;
constexpr int A_KV   = A_QL  + 128 * 72 * 2;       // [2 stages][Kh,Kl,Vh,Vl][64][72]
constexpr int A_KV1  = 64 * 72 * 2;                // one array
constexpr int A_STG  = 4 * A_KV1;                  // one stage
constexpr int A_S    = A_KV  + 2 * A_STG;          // Sm[128][68] f32
constexpr int A_PH   = A_S   + 128 * 68 * 4;
constexpr int A_PL   = A_PH  + 128 * 72 * 2;
constexpr int A_L    = A_PL  + 128 * 72 * 2;       // linv[128]
constexpr int ATTN_SMEM = A_L + 128 * 4;           // ~179 KB

__global__ __launch_bounds__(256) void attn_fused_kernel(
    size_t qhi_off, size_t qlo_off, size_t khi_off, size_t klo_off,
    size_t vhi_off, size_t vlo_off,
    const int* __restrict__ mask, float* __restrict__ attn,
    size_t xhhi_off, size_t xhlo_off)
{
    extern __shared__ unsigned char smraw[];
    __nv_bfloat16* Qh = (__nv_bfloat16*)(smraw + A_Q);
    __nv_bfloat16* Ql = (__nv_bfloat16*)(smraw + A_QL);
    float*         Sm = (float*)(smraw + A_S);
    __nv_bfloat16* Ph = (__nv_bfloat16*)(smraw + A_PH);
    __nv_bfloat16* Pl = (__nv_bfloat16*)(smraw + A_PL);
    float*         lrowinv = (float*)(smraw + A_L);

    const __nv_bfloat16* Qhi = (const __nv_bfloat16*)(g_arena + qhi_off);
    const __nv_bfloat16* Qlo = (const __nv_bfloat16*)(g_arena + qlo_off);
    const __nv_bfloat16* Khi = (const __nv_bfloat16*)(g_arena + khi_off);
    const __nv_bfloat16* Klo = (const __nv_bfloat16*)(g_arena + klo_off);
    const __nv_bfloat16* Vhi = (const __nv_bfloat16*)(g_arena + vhi_off);
    const __nv_bfloat16* Vlo = (const __nv_bfloat16*)(g_arena + vlo_off);

    int bh = blockIdx.y;
    int b = bh >> 4, h = bh & 15;
    int q0 = blockIdx.x * 128;
    int tid = threadIdx.x, wid = tid >> 5, lane = tid & 31;
    int wm = wid & 3, wn = wid >> 2;   // warp tile 32(m) x 32(n) in 128x64

    // prefetch one stage of K+V (hi/lo), 64 kv-rows
    auto prefetch_kv = [&](int st, int kt) {
        size_t gbase = ((size_t)b * S + kt * 64) * D + h * HD;
        uint32_t kh = (unsigned)__cvta_generic_to_shared(smraw + A_KV + st * A_STG);
#pragma unroll
        for (int i = 0; i < 2; i++) {
            int v = tid + 256 * i;
            int r = v >> 3, c = (v & 7) * 8;       // r 0..63, c 0,8,..,56
            size_t g = gbase + (size_t)r * D + c;
            uint32_t so = (uint32_t)(r * 72 + c) * 2;
            CP_ASYNC16(kh + so,              Khi + g);
            CP_ASYNC16(kh + A_KV1 + so,      Klo + g);
            CP_ASYNC16(kh + 2 * A_KV1 + so,  Vhi + g);
            CP_ASYNC16(kh + 3 * A_KV1 + so,  Vlo + g);
        }
    };

    // load Q tile (128x64) hi/lo
    size_t qbase = ((size_t)b * S + q0) * D + h * HD;
#pragma unroll
    for (int i = 0; i < 8; i++) {
        int v = tid + 256 * i;
        int r = v >> 4, c = (v & 15) * 4;
        *(uint2*)&Qh[r * 72 + c] = *(const uint2*)(Qhi + qbase + (size_t)r * D + c);
        *(uint2*)&Ql[r * 72 + c] = *(const uint2*)(Qlo + qbase + (size_t)r * D + c);
    }

    float tsum[16];
#pragma unroll
    for (int i = 0; i < 16; i++) tsum[i] = 0.0f;

    wmma::fragment<wmma::accumulator, 16, 16, 16, float> accO[2][2];
#pragma unroll
    for (int i = 0; i < 2; i++)
#pragma unroll
        for (int j = 0; j < 2; j++) wmma::fill_fragment(accO[i][j], 0.0f);

    prefetch_kv(0, 0);
    CP_COMMIT();
    __syncthreads();   // Q ready (also covered by first wait)

    for (int kt = 0; kt < 32; kt++) {
        if (kt < 31) prefetch_kv((kt + 1) & 1, kt + 1);
        CP_COMMIT();
        CP_WAIT1();
        __syncthreads();
        int st = kt & 1;
        const __nv_bfloat16* Kh = (const __nv_bfloat16*)(smraw + A_KV + st * A_STG);
        const __nv_bfloat16* Kl = Kh + 64 * 72;
        const __nv_bfloat16* Vh = Kh + 2 * 64 * 72;
        const __nv_bfloat16* Vl = Kh + 3 * 64 * 72;

        // ---- S = Q K^T / 8 ----
        wmma::fragment<wmma::accumulator, 16, 16, 16, float> acc[2][2];
#pragma unroll
        for (int i = 0; i < 2; i++)
#pragma unroll
            for (int j = 0; j < 2; j++) wmma::fill_fragment(acc[i][j], 0.0f);
#pragma unroll
        for (int kk = 0; kk < HD; kk += 16) {
            wmma::fragment<wmma::matrix_a, 16, 16, 16, __nv_bfloat16, wmma::row_major> ah[2], al[2];
            wmma::fragment<wmma::matrix_b, 16, 16, 16, __nv_bfloat16, wmma::col_major> bh_[2], bl_[2];
#pragma unroll
            for (int i = 0; i < 2; i++) {
                wmma::load_matrix_sync(ah[i], Qh + (wm * 32 + i * 16) * 72 + kk, 72);
                wmma::load_matrix_sync(al[i], Ql + (wm * 32 + i * 16) * 72 + kk, 72);
            }
#pragma unroll
            for (int j = 0; j < 2; j++) {
                wmma::load_matrix_sync(bh_[j], Kh + (wn * 32 + j * 16) * 72 + kk, 72);
                wmma::load_matrix_sync(bl_[j], Kl + (wn * 32 + j * 16) * 72 + kk, 72);
            }
#pragma unroll
            for (int i = 0; i < 2; i++)
#pragma unroll
                for (int j = 0; j < 2; j++) {
                    wmma::mma_sync(acc[i][j], ah[i], bh_[j], acc[i][j]);
                    wmma::mma_sync(acc[i][j], ah[i], bl_[j], acc[i][j]);
                    wmma::mma_sync(acc[i][j], al[i], bh_[j], acc[i][j]);
                }
        }
#pragma unroll
        for (int i = 0; i < 2; i++)
#pragma unroll
            for (int j = 0; j < 2; j++) {
                for (int t = 0; t < acc[i][j].num_elements; t++) acc[i][j].x[t] *= 0.125f;
                wmma::store_matrix_sync(Sm + (wm * 32 + i * 16) * 68 + wn * 32 + j * 16,
                                        acc[i][j], 68, wmma::mem_row_major);
            }
        __syncthreads();

        // ---- p' = exp(s) (masked), raw write, row-sum, P hi/lo ----
        int colb = kt * 64;
        const int* mk = mask + (size_t)b * S + colb;
        bool z0 = (mk[lane] == 0), z1 = (mk[lane + 32] == 0);
#pragma unroll
        for (int r16 = 0; r16 < 16; r16++) {
            int row = wid * 16 + r16;
            float p0 = z0 ? 0.0f : __expf(Sm[row * 68 + lane]);
            float p1 = z1 ? 0.0f : __expf(Sm[row * 68 + lane + 32]);
            float* arow = attn + ((size_t)bh * S + q0 + row) * S + colb;
            arow[lane] = p0;
            arow[lane + 32] = p1;
            tsum[r16] += p0 + p1;
            __nv_bfloat16 h0 = __float2bfloat16(p0);
            __nv_bfloat16 h1 = __float2bfloat16(p1);
            Ph[row * 72 + lane] = h0;
            Ph[row * 72 + lane + 32] = h1;
            Pl[row * 72 + lane] = __float2bfloat16(p0 - __bfloat162float(h0));
            Pl[row * 72 + lane + 32] = __float2bfloat16(p1 - __bfloat162float(h1));
        }
        __syncthreads();

        // ---- O += P' V ----
#pragma unroll
        for (int kk = 0; kk < 64; kk += 16) {
            wmma::fragment<wmma::matrix_a, 16, 16, 16, __nv_bfloat16, wmma::row_major> ah[2], al[2];
            wmma::fragment<wmma::matrix_b, 16, 16, 16, __nv_bfloat16, wmma::row_major> bh_[2], bl_[2];
#pragma unroll
            for (int i = 0; i < 2; i++) {
                wmma::load_matrix_sync(ah[i], Ph + (wm * 32 + i * 16) * 72 + kk, 72);
                wmma::load_matrix_sync(al[i], Pl + (wm * 32 + i * 16) * 72 + kk, 72);
            }
#pragma unroll
            for (int j = 0; j < 2; j++) {
                wmma::load_matrix_sync(bh_[j], Vh + kk * 72 + wn * 32 + j * 16, 72);
                wmma::load_matrix_sync(bl_[j], Vl + kk * 72 + wn * 32 + j * 16, 72);
            }
#pragma unroll
            for (int i = 0; i < 2; i++)
#pragma unroll
                for (int j = 0; j < 2; j++) {
                    wmma::mma_sync(accO[i][j], ah[i], bh_[j], accO[i][j]);
                    wmma::mma_sync(accO[i][j], ah[i], bl_[j], accO[i][j]);
                    wmma::mma_sync(accO[i][j], al[i], bh_[j], accO[i][j]);
                }
        }
        __syncthreads();
    }

    // ---- reduce row sums, store 1/l ----
    float* Linv = (float*)(g_arena + OFF_LINV);
#pragma unroll
    for (int r16 = 0; r16 < 16; r16++) {
        float s = tsum[r16];
#pragma unroll
        for (int o = 16; o; o >>= 1) s += __shfl_xor_sync(0xffffffffu, s, o);
        if (lane == 0) {
            int row = wid * 16 + r16;
            float inv = 1.0f / s;
            lrowinv[row] = inv;
            Linv[(size_t)bh * S + q0 + row] = inv;
        }
    }
    __syncthreads();

    // ---- O scale + write XH hi/lo ----
#pragma unroll
    for (int i = 0; i < 2; i++)
#pragma unroll
        for (int j = 0; j < 2; j++)
            wmma::store_matrix_sync(Sm + (wm * 32 + i * 16) * 68 + wn * 32 + j * 16,
                                    accO[i][j], 68, wmma::mem_row_major);
    __syncthreads();

    __nv_bfloat16* XHhi = (__nv_bfloat16*)(g_arena + xhhi_off);
    __nv_bfloat16* XHlo = (__nv_bfloat16*)(g_arena + xhlo_off);
#pragma unroll
    for (int i = 0; i < 32; i++) {
        int v = tid + 256 * i;     // 0..8191
        int r = v >> 6, c = v & 63;
        float x = Sm[r * 68 + c] * lrowinv[r];
        __nv_bfloat16 hh = __float2bfloat16(x);
        size_t g = ((size_t)b * S + q0 + r) * D + h * HD + c;
        XHhi[g] = hh;
        XHlo[g] = __float2bfloat16(x - __bfloat162float(hh));
    }
}

// ---------------- normalize: attn[row][*] *= linv[row], streaming ----------
__global__ void normalize_kernel(float* __restrict__ attn)
{
    const float* Linv = (const float*)(g_arena + OFF_LINV);
    size_t i4 = (size_t)blockIdx.x * blockDim.x + threadIdx.x;   // float4 index
    size_t row = i4 >> 9;                                        // S/4 = 512 float4 per row
    float il = Linv[row];
    float4 v = ((const float4*)attn)[i4];
    v.x *= il; v.y *= il; v.z *= il; v.w *= il;
    ((float4*)attn)[i4] = v;
}

// ---------------- launch ----------------
extern "C" void kernel_launch(void* const* d_in, const int* in_sizes, int n_in,
                              void* d_out, int out_size)
{
    const float* query = (const float*)d_in[0];
    const float* key   = (const float*)d_in[1];
    const float* value = (const float*)d_in[2];
    const int*   mask  = (const int*)d_in[3];
    const float* Wq    = (const float*)d_in[4];
    const float* bq    = (const float*)d_in[5];
    const float* Wk    = (const float*)d_in[6];
    const float* bk    = (const float*)d_in[7];
    const float* Wv    = (const float*)d_in[8];
    const float* bv    = (const float*)d_in[9];
    const float* Wo    = (const float*)d_in[10];
    const float* bo    = (const float*)d_in[11];

    float* out_x = (float*)d_out;            // [B,S,D]
    float* attn  = out_x + NEL;              // [B,H,S,S]

    cudaFuncSetAttribute(gemm_kernel, cudaFuncAttributeMaxDynamicSharedMemorySize, GEMM_SMEM);
    cudaFuncSetAttribute(attn_fused_kernel, cudaFuncAttributeMaxDynamicSharedMemorySize, ATTN_SMEM);

    int nblk = (int)(NEL / 256);
    int wblk = (int)(WEL / 256);

    split_kernel<<<nblk, 256>>>(query, OFF_IN_HI + 0 * NEL * 2, OFF_IN_LO + 0 * NEL * 2, (int)NEL);
    split_kernel<<<nblk, 256>>>(key,   OFF_IN_HI + 1 * NEL * 2, OFF_IN_LO + 1 * NEL * 2, (int)NEL);
    split_kernel<<<nblk, 256>>>(value, OFF_IN_HI + 2 * NEL * 2, OFF_IN_LO + 2 * NEL * 2, (int)NEL);
    split_kernel<<<wblk, 256>>>(Wq, OFF_W_HI + 0 * WEL * 2, OFF_W_LO + 0 * WEL * 2, (int)WEL);
    split_kernel<<<wblk, 256>>>(Wk, OFF_W_HI + 1 * WEL * 2, OFF_W_LO + 1 * WEL * 2, (int)WEL);
    split_kernel<<<wblk, 256>>>(Wv, OFF_W_HI + 2 * WEL * 2, OFF_W_LO + 2 * WEL * 2, (int)WEL);
    split_kernel<<<wblk, 256>>>(Wo, OFF_W_HI + 3 * WEL * 2, OFF_W_LO + 3 * WEL * 2, (int)WEL);

    dim3 ggrid(D / 64, (B * S) / 128);   // (16, 32)
    gemm_kernel<<<ggrid, 256, GEMM_SMEM>>>(OFF_IN_HI + 0 * NEL * 2, OFF_IN_LO + 0 * NEL * 2,
                                           OFF_W_HI + 0 * WEL * 2, OFF_W_LO + 0 * WEL * 2,
                                           bq, nullptr, OFF_QKV_HI + 0 * NEL * 2, OFF_QKV_LO + 0 * NEL * 2);
    gemm_kernel<<<ggrid, 256, GEMM_SMEM>>>(OFF_IN_HI + 1 * NEL * 2, OFF_IN_LO + 1 * NEL * 2,
                                           OFF_W_HI + 1 * WEL * 2, OFF_W_LO + 1 * WEL * 2,
                                           bk, nullptr, OFF_QKV_HI + 1 * NEL * 2, OFF_QKV_LO + 1 * NEL * 2);
    gemm_kernel<<<ggrid, 256, GEMM_SMEM>>>(OFF_IN_HI + 2 * NEL * 2, OFF_IN_LO + 2 * NEL * 2,
                                           OFF_W_HI + 2 * WEL * 2, OFF_W_LO + 2 * WEL * 2,
                                           bv, nullptr, OFF_QKV_HI + 2 * NEL * 2, OFF_QKV_LO + 2 * NEL * 2);

    // single-pass attention (writes unnormalized exp to attn, XH hi/lo, 1/l)
    attn_fused_kernel<<<dim3(S / 128, B * H), 256, ATTN_SMEM>>>(
        OFF_QKV_HI + 0 * NEL * 2, OFF_QKV_LO + 0 * NEL * 2,
        OFF_QKV_HI + 1 * NEL * 2, OFF_QKV_LO + 1 * NEL * 2,
        OFF_QKV_HI + 2 * NEL * 2, OFF_QKV_LO + 2 * NEL * 2,
        mask, attn, OFF_XH_HI, OFF_XH_LO);

    // streaming normalize of attn
    size_t n4 = ((size_t)B * H * S * S) / 4;
    normalize_kernel<<<(unsigned)(n4 / 256), 256>>>(attn);

    // output projection
    gemm_kernel<<<ggrid, 256, GEMM_SMEM>>>(OFF_XH_HI, OFF_XH_LO,
                                           OFF_W_HI + 3 * WEL * 2, OFF_W_LO + 3 * WEL * 2,
                                           bo, out_x, 0, 0);
}